// round 1
// baseline (speedup 1.0000x reference)
#include <cuda_runtime.h>

// SCSA fused kernel for GB300.
// x: (32, 512, 64, 64) f32. G=8, cg=32, HW=64x64=4096.
// Grid: 512 CTAs. blockIdx.x>>1 = block b in [0,256) (b = n*8+g);
// blockIdx.x&1 = branch (0=channel/x0, 1=spatial/x1).
// 1024 threads = 32 warps; warp w owns channel w of its 32-channel half.
// Dynamic smem sized to 120KB to force occupancy 1 -> per-wave working set
// 148 CTAs * 512KB = 74MB < 126MB L2, so the second read of x hits L2.

#define THREADS 1024
#define SMEM_BYTES (120 * 1024)

__device__ __forceinline__ float sigmoidf_(float z) {
    return 1.f / (1.f + __expf(-z));
}

__device__ __forceinline__ float hswishf_(float z) {
    // z * clip(z+3, 0, 6) / 6 == z * saturate((z+3)/6)
    return z * __saturatef((z + 3.f) * (1.f / 6.f));
}

__device__ __forceinline__ int shuffle_out_ch(int p) {
    // out.reshape(n,2,256,h,w).transpose(0,2,1,3,4): pre-ch p -> out-ch
    return (p < 256) ? (2 * p) : (2 * (p - 256) + 1);
}

__global__ __launch_bounds__(THREADS, 1) void scsa_kernel(
    const float* __restrict__ x,
    const float* __restrict__ cweight, const float* __restrict__ cbias,
    const float* __restrict__ conv1_w, const float* __restrict__ conv1_b,
    const float* __restrict__ gn_g,    const float* __restrict__ gn_b,
    const float* __restrict__ convh_w, const float* __restrict__ convh_b,
    const float* __restrict__ convw_w, const float* __restrict__ convw_b,
    float* __restrict__ out)
{
    const int b      = blockIdx.x >> 1;
    const int branch = blockIdx.x & 1;
    const int n = b >> 3;
    const int g = b & 7;
    const int tid  = threadIdx.x;
    const int wid  = tid >> 5;   // warp id = channel within half-group
    const int lane = tid & 31;

    if (branch == 0) {
        // ---------------- channel branch (x0, channels g*64 + [0,32)) ----
        // Each warp is fully independent: GAP -> sigmoid gate -> scale.
        const float4* xc = (const float4*)(x + ((size_t)(n * 512 + g * 64 + wid)) * 4096);
        float s = 0.f;
        #pragma unroll 8
        for (int i = 0; i < 32; i++) {
            float4 v = xc[i * 32 + lane];
            s += (v.x + v.y) + (v.z + v.w);
        }
        #pragma unroll
        for (int o = 16; o; o >>= 1) s += __shfl_xor_sync(0xffffffffu, s, o);
        const float gap  = s * (1.f / 4096.f);
        const float gate = sigmoidf_(cweight[wid] * gap + cbias[wid]);

        const int p  = g * 64 + wid;
        const int oc = shuffle_out_ch(p);
        float4* od = (float4*)(out + ((size_t)(n * 512 + oc)) * 4096);
        #pragma unroll 8
        for (int i = 0; i < 32; i++) {
            float4 v = xc[i * 32 + lane];
            v.x *= gate; v.y *= gate; v.z *= gate; v.w *= gate;
            od[i * 32 + lane] = v;
        }
        return;
    }

    // ---------------- spatial branch (x1, channels g*64 + 32 + [0,32)) ----
    extern __shared__ float sm[];
    float* s_xh = sm;             // [32][64] row means
    float* s_xw = sm + 2048;      // [32][64] col means
    float* s_y  = sm + 4096;      // [32][128] conv1/gn/hswish buffer
    float* s_ah = sm + 8192;      // [32][64]
    float* s_aw = sm + 10240;     // [32][64]
    float* s_xs = sm + 12288;     // [32]
    float* s_w1 = sm + 12320;     // [32*32]
    float* s_wh = sm + 13344;     // [32*32]
    float* s_ww = sm + 14368;     // [32*32]
    float* s_b1 = sm + 15392;     // [32]
    float* s_bh = sm + 15424;     // [32]
    float* s_bw = sm + 15456;     // [32]
    float* s_gg = sm + 15488;     // [32]
    float* s_gb = sm + 15520;     // [32]

    // stage weights (independent of x)
    s_w1[tid] = conv1_w[tid];
    s_wh[tid] = convh_w[tid];
    s_ww[tid] = convw_w[tid];
    if (tid < 32) {
        s_b1[tid] = conv1_b[tid];
        s_bh[tid] = convh_b[tid];
        s_bw[tid] = convw_b[tid];
        s_gg[tid] = gn_g[tid];
        s_gb[tid] = gn_b[tid];
    }

    const float* xc = x + ((size_t)(n * 512 + g * 64 + 32 + wid)) * 4096;

    // Pass A: per-channel reductions. Warp w scans channel w's 64x64 image.
    // Lane l covers columns 2l, 2l+1 (float2 -> 256B coalesced per row).
    float col0 = 0.f, col1 = 0.f;
    #pragma unroll 4
    for (int h = 0; h < 64; h++) {
        float2 v = ((const float2*)(xc + h * 64))[lane];
        col0 += v.x; col1 += v.y;
        float rs = v.x + v.y;
        #pragma unroll
        for (int o = 16; o; o >>= 1) rs += __shfl_xor_sync(0xffffffffu, rs, o);
        if (lane == 0) s_xh[wid * 64 + h] = rs * (1.f / 64.f);
    }
    s_xw[wid * 64 + 2 * lane]     = col0 * (1.f / 64.f);
    s_xw[wid * 64 + 2 * lane + 1] = col1 * (1.f / 64.f);
    float cs = col0 + col1;
    #pragma unroll
    for (int o = 16; o; o >>= 1) cs += __shfl_xor_sync(0xffffffffu, cs, o);
    if (lane == 0) s_xs[wid] = cs * (1.f / 4096.f);
    __syncthreads();

    // conv1: y2[o][p] = b1[o] + sum_i w1[o][i] * y[i][p], y = [x_h | x_w]
    for (int idx = tid; idx < 4096; idx += THREADS) {
        const int o = idx >> 7, p = idx & 127;
        const float* yb = (p < 64) ? (s_xh + p) : (s_xw + (p - 64));
        float acc = s_b1[o];
        #pragma unroll
        for (int i = 0; i < 32; i++) acc = fmaf(s_w1[o * 32 + i], yb[i * 64], acc);
        s_y[o * 128 + p] = acc;
    }
    __syncthreads();

    // GroupNorm over 128 positions per channel + h-swish. Warp w -> channel w.
    {
        const float* yr = s_y + wid * 128;
        float v0 = yr[lane], v1 = yr[lane + 32], v2 = yr[lane + 64], v3 = yr[lane + 96];
        float s1 = (v0 + v1) + (v2 + v3);
        float s2 = v0 * v0 + v1 * v1 + v2 * v2 + v3 * v3;
        #pragma unroll
        for (int o = 16; o; o >>= 1) {
            s1 += __shfl_xor_sync(0xffffffffu, s1, o);
            s2 += __shfl_xor_sync(0xffffffffu, s2, o);
        }
        const float mu  = s1 * (1.f / 128.f);
        const float var = s2 * (1.f / 128.f) - mu * mu;
        const float inv = rsqrtf(var + 1e-5f);
        const float gm  = s_gg[wid] * inv;
        const float gc  = s_gb[wid] - mu * gm;
        float* yw = s_y + wid * 128;
        yw[lane]      = hswishf_(fmaf(v0, gm, gc));
        yw[lane + 32] = hswishf_(fmaf(v1, gm, gc));
        yw[lane + 64] = hswishf_(fmaf(v2, gm, gc));
        yw[lane + 96] = hswishf_(fmaf(v3, gm, gc));
    }
    __syncthreads();

    // conv_h on positions [0,64), conv_w on [64,128)
    for (int idx = tid; idx < 4096; idx += THREADS) {
        const int o = idx >> 7, p = idx & 127;
        if (p < 64) {
            float acc = s_bh[o];
            #pragma unroll
            for (int i = 0; i < 32; i++) acc = fmaf(s_wh[o * 32 + i], s_y[i * 128 + p], acc);
            s_ah[o * 64 + p] = acc;
        } else {
            float acc = s_bw[o];
            #pragma unroll
            for (int i = 0; i < 32; i++) acc = fmaf(s_ww[o * 32 + i], s_y[i * 128 + p], acc);
            s_aw[o * 64 + (p - 64)] = acc;
        }
    }
    __syncthreads();

    // Pass B: x_spatial = x1 * sigmoid(a_h[h] * a_w[w] * x_s), written to
    // the channel-shuffled output position. Second read of xc hits L2.
    const float xsv = s_xs[wid];
    const float gw0 = s_aw[wid * 64 + 2 * lane]     * xsv;
    const float gw1 = s_aw[wid * 64 + 2 * lane + 1] * xsv;
    const int p  = g * 64 + 32 + wid;
    const int oc = shuffle_out_ch(p);
    float* od = out + ((size_t)(n * 512 + oc)) * 4096;
    #pragma unroll 4
    for (int h = 0; h < 64; h++) {
        const float ahv = s_ah[wid * 64 + h];
        float2 v = ((const float2*)(xc + h * 64))[lane];
        v.x *= sigmoidf_(ahv * gw0);
        v.y *= sigmoidf_(ahv * gw1);
        ((float2*)(od + h * 64))[lane] = v;
    }
}

extern "C" void kernel_launch(void* const* d_in, const int* in_sizes, int n_in,
                              void* d_out, int out_size) {
    const float* x       = (const float*)d_in[0];
    const float* cweight = (const float*)d_in[1];
    const float* cbias   = (const float*)d_in[2];
    const float* conv1_w = (const float*)d_in[3];
    const float* conv1_b = (const float*)d_in[4];
    const float* gn_g    = (const float*)d_in[5];
    const float* gn_b    = (const float*)d_in[6];
    const float* convh_w = (const float*)d_in[7];
    const float* convh_b = (const float*)d_in[8];
    const float* convw_w = (const float*)d_in[9];
    const float* convw_b = (const float*)d_in[10];
    float* out = (float*)d_out;

    cudaFuncSetAttribute(scsa_kernel, cudaFuncAttributeMaxDynamicSharedMemorySize,
                         SMEM_BYTES);
    scsa_kernel<<<512, THREADS, SMEM_BYTES>>>(
        x, cweight, cbias, conv1_w, conv1_b, gn_g, gn_b,
        convh_w, convh_b, convw_w, convw_b, out);
}

// round 2
// speedup vs baseline: 1.0421x; 1.0421x over previous
#include <cuda_runtime.h>

// SCSA fused kernel v2.
// Grid 512: blockIdx>>1 = block b (n*8+g), blockIdx&1 = branch (0=channel x0, 1=spatial x1).
// 512 threads (16 warps), occ 3 per SM -> 444 resident CTAs, L2-reuse of per-CTA
// 128KB tile between reduce pass and apply pass preserved (57MB < 126MB L2).

#define THREADS 512

__device__ __forceinline__ float sigmoidf_(float z) {
    return 1.f / (1.f + __expf(-z));
}
// fast sigmoid via HW tanh: sigmoid(z) = 0.5*tanh(z/2) + 0.5
__device__ __forceinline__ float sigapx_(float z) {
    float t;
    asm("tanh.approx.f32 %0, %1;" : "=f"(t) : "f"(z * 0.5f));
    return fmaf(0.5f, t, 0.5f);
}
__device__ __forceinline__ float hswishf_(float z) {
    return z * __saturatef((z + 3.f) * (1.f / 6.f));
}
__device__ __forceinline__ int shuffle_out_ch(int p) {
    return (p < 256) ? (2 * p) : (2 * (p - 256) + 1);
}

__global__ __launch_bounds__(THREADS, 3) void scsa_kernel(
    const float* __restrict__ x,
    const float* __restrict__ cweight, const float* __restrict__ cbias,
    const float* __restrict__ conv1_w, const float* __restrict__ conv1_b,
    const float* __restrict__ gn_g,    const float* __restrict__ gn_b,
    const float* __restrict__ convh_w, const float* __restrict__ convh_b,
    const float* __restrict__ convw_w, const float* __restrict__ convw_b,
    float* __restrict__ out)
{
    const int b      = blockIdx.x >> 1;
    const int branch = blockIdx.x & 1;
    const int n = b >> 3;
    const int g = b & 7;
    const int tid  = threadIdx.x;
    const int wid  = tid >> 5;          // 0..15
    const int lane = tid & 31;
    const int half = lane >> 4;         // 0: even row, 1: odd row
    const int q    = lane & 15;         // position within half-warp

    if (branch == 0) {
        // ============ channel branch: x0 = channels g*64 + [0,32) ============
        const int c0 = 2 * wid, c1 = c0 + 1;
        const float4* xa = (const float4*)(x + ((size_t)(n * 512 + g * 64 + c0)) * 4096);
        const float4* xb = xa + 1024;
        float sa = 0.f, sb = 0.f;
        #pragma unroll 4
        for (int i = 0; i < 32; i++) {
            float4 va = xa[i * 32 + lane];
            float4 vb = xb[i * 32 + lane];
            sa += (va.x + va.y) + (va.z + va.w);
            sb += (vb.x + vb.y) + (vb.z + vb.w);
        }
        #pragma unroll
        for (int o = 16; o; o >>= 1) {
            sa += __shfl_xor_sync(0xffffffffu, sa, o);
            sb += __shfl_xor_sync(0xffffffffu, sb, o);
        }
        const float ga = sigmoidf_(cweight[c0] * (sa * (1.f / 4096.f)) + cbias[c0]);
        const float gb = sigmoidf_(cweight[c1] * (sb * (1.f / 4096.f)) + cbias[c1]);

        float4* oa = (float4*)(out + ((size_t)(n * 512 + shuffle_out_ch(g * 64 + c0))) * 4096);
        float4* ob = (float4*)(out + ((size_t)(n * 512 + shuffle_out_ch(g * 64 + c1))) * 4096);
        #pragma unroll 4
        for (int i = 0; i < 32; i++) {
            float4 va = xa[i * 32 + lane];
            float4 vb = xb[i * 32 + lane];
            va.x *= ga; va.y *= ga; va.z *= ga; va.w *= ga;
            vb.x *= gb; vb.y *= gb; vb.z *= gb; vb.w *= gb;
            oa[i * 32 + lane] = va;
            ob[i * 32 + lane] = vb;
        }
        return;
    }

    // ============ spatial branch: x1 = channels g*64 + 32 + [0,32) ============
    __shared__ float s_red[32 * 128];   // xh (cols 0-63) | xw (cols 64-127); later aliased as a_h|a_w
    __shared__ float s_y[32 * 128];
    __shared__ float s_w1[1024], s_wh[1024], s_ww[1024];
    __shared__ float s_b1[32], s_bh[32], s_bw[32], s_gg[32], s_gb[32], s_xs[32];
    float* s_a = s_red;                 // alias: s_red dead after conv1

    // stage weights
    for (int i = tid; i < 1024; i += THREADS) {
        s_w1[i] = conv1_w[i];
        s_wh[i] = convh_w[i];
        s_ww[i] = convw_w[i];
    }
    if (tid < 32) {
        s_b1[tid] = conv1_b[tid]; s_bh[tid] = convh_b[tid]; s_bw[tid] = convw_b[tid];
        s_gg[tid] = gn_g[tid];    s_gb[tid] = gn_b[tid];
    }

    const int c0 = 2 * wid, c1 = c0 + 1;
    const float4* xa = (const float4*)(x + ((size_t)(n * 512 + g * 64 + 32 + c0)) * 4096);
    const float4* xb = xa + 1024;

    // -------- Pass A: row means, col means, total mean --------
    // One LDG.128 per channel per iter covers rows 2t (lanes 0-15) and 2t+1
    // (lanes 16-31): 512 contiguous bytes. Row sum = 4-level half-warp butterfly.
    float a0 = 0.f, a1 = 0.f, a2 = 0.f, a3 = 0.f;
    float b0 = 0.f, b1 = 0.f, b2 = 0.f, b3 = 0.f;
    float xsa = 0.f, xsb = 0.f;
    for (int t = 0; t < 32; t++) {
        float4 va = xa[t * 32 + lane];
        float4 vb = xb[t * 32 + lane];
        a0 += va.x; a1 += va.y; a2 += va.z; a3 += va.w;
        b0 += vb.x; b1 += vb.y; b2 += vb.z; b3 += vb.w;
        float ra = (va.x + va.y) + (va.z + va.w);
        float rb = (vb.x + vb.y) + (vb.z + vb.w);
        xsa += ra; xsb += rb;
        #pragma unroll
        for (int o = 8; o; o >>= 1) {
            ra += __shfl_xor_sync(0xffffffffu, ra, o);
            rb += __shfl_xor_sync(0xffffffffu, rb, o);
        }
        if (q == 0) {
            s_red[c0 * 128 + 2 * t + half] = ra * (1.f / 64.f);
            s_red[c1 * 128 + 2 * t + half] = rb * (1.f / 64.f);
        }
    }
    // fold odd-row half into even-row half for col sums
    a0 += __shfl_xor_sync(0xffffffffu, a0, 16);
    a1 += __shfl_xor_sync(0xffffffffu, a1, 16);
    a2 += __shfl_xor_sync(0xffffffffu, a2, 16);
    a3 += __shfl_xor_sync(0xffffffffu, a3, 16);
    b0 += __shfl_xor_sync(0xffffffffu, b0, 16);
    b1 += __shfl_xor_sync(0xffffffffu, b1, 16);
    b2 += __shfl_xor_sync(0xffffffffu, b2, 16);
    b3 += __shfl_xor_sync(0xffffffffu, b3, 16);
    #pragma unroll
    for (int o = 16; o; o >>= 1) {
        xsa += __shfl_xor_sync(0xffffffffu, xsa, o);
        xsb += __shfl_xor_sync(0xffffffffu, xsb, o);
    }
    if (half == 0) {
        const float inv = 1.f / 64.f;
        ((float4*)(s_red + c0 * 128 + 64))[q] = make_float4(a0 * inv, a1 * inv, a2 * inv, a3 * inv);
        ((float4*)(s_red + c1 * 128 + 64))[q] = make_float4(b0 * inv, b1 * inv, b2 * inv, b3 * inv);
    }
    if (lane == 0) {
        s_xs[c0] = xsa * (1.f / 4096.f);
        s_xs[c1] = xsb * (1.f / 4096.f);
    }
    __syncthreads();

    // -------- conv1: y[o][p] = b1[o] + sum_i w1[o][i]*red[i][p] --------
    #pragma unroll
    for (int it = 0; it < 8; it++) {
        const int idx = it * THREADS + tid;
        const int o = idx >> 7, p = idx & 127;
        float acc = s_b1[o];
        #pragma unroll
        for (int i = 0; i < 32; i++) acc = fmaf(s_w1[o * 32 + i], s_red[i * 128 + p], acc);
        s_y[idx] = acc;
    }
    __syncthreads();

    // -------- GroupNorm(128 positions per channel) + h-swish --------
    {
        #pragma unroll
        for (int cc = 0; cc < 2; cc++) {
            const int c = c0 + cc;
            float* yr = s_y + c * 128;
            float v0 = yr[lane], v1 = yr[lane + 32], v2 = yr[lane + 64], v3 = yr[lane + 96];
            float s1 = (v0 + v1) + (v2 + v3);
            float s2 = fmaf(v0, v0, fmaf(v1, v1, fmaf(v2, v2, v3 * v3)));
            #pragma unroll
            for (int o = 16; o; o >>= 1) {
                s1 += __shfl_xor_sync(0xffffffffu, s1, o);
                s2 += __shfl_xor_sync(0xffffffffu, s2, o);
            }
            const float mu  = s1 * (1.f / 128.f);
            const float var = s2 * (1.f / 128.f) - mu * mu;
            const float gm  = s_gg[c] * rsqrtf(var + 1e-5f);
            const float gc  = fmaf(-mu, gm, s_gb[c]);
            yr[lane]      = hswishf_(fmaf(v0, gm, gc));
            yr[lane + 32] = hswishf_(fmaf(v1, gm, gc));
            yr[lane + 64] = hswishf_(fmaf(v2, gm, gc));
            yr[lane + 96] = hswishf_(fmaf(v3, gm, gc));
        }
    }
    __syncthreads();

    // -------- conv_h (positions 0-63) / conv_w (64-127) -> s_a (alias s_red) --------
    #pragma unroll
    for (int it = 0; it < 8; it++) {
        const int idx = it * THREADS + tid;
        const int o = idx >> 7, p = idx & 127;
        const float* w = (p < 64) ? (s_wh + o * 32) : (s_ww + o * 32);
        float acc = (p < 64) ? s_bh[o] : s_bw[o];
        #pragma unroll
        for (int i = 0; i < 32; i++) acc = fmaf(w[i], s_y[i * 128 + p], acc);
        s_a[idx] = acc;
    }
    __syncthreads();

    // -------- Pass B: out = x1 * sigmoid(a_h[h]*a_w[w]*x_s), channel-shuffled --------
    const float xs0 = s_xs[c0], xs1 = s_xs[c1];
    float4 awa = ((const float4*)(s_a + c0 * 128 + 64))[q];
    float4 awb = ((const float4*)(s_a + c1 * 128 + 64))[q];
    const float ga0 = awa.x * xs0, ga1 = awa.y * xs0, ga2 = awa.z * xs0, ga3 = awa.w * xs0;
    const float gb0 = awb.x * xs1, gb1 = awb.y * xs1, gb2 = awb.z * xs1, gb3 = awb.w * xs1;

    float4* oa = (float4*)(out + ((size_t)(n * 512 + shuffle_out_ch(g * 64 + 32 + c0))) * 4096);
    float4* ob = (float4*)(out + ((size_t)(n * 512 + shuffle_out_ch(g * 64 + 32 + c1))) * 4096);
    for (int t = 0; t < 32; t++) {
        float4 va = xa[t * 32 + lane];
        float4 vb = xb[t * 32 + lane];
        const float aha = s_a[c0 * 128 + 2 * t + half];
        const float ahb = s_a[c1 * 128 + 2 * t + half];
        va.x *= sigapx_(aha * ga0); va.y *= sigapx_(aha * ga1);
        va.z *= sigapx_(aha * ga2); va.w *= sigapx_(aha * ga3);
        vb.x *= sigapx_(ahb * gb0); vb.y *= sigapx_(ahb * gb1);
        vb.z *= sigapx_(ahb * gb2); vb.w *= sigapx_(ahb * gb3);
        oa[t * 32 + lane] = va;
        ob[t * 32 + lane] = vb;
    }
}

extern "C" void kernel_launch(void* const* d_in, const int* in_sizes, int n_in,
                              void* d_out, int out_size) {
    const float* x       = (const float*)d_in[0];
    const float* cweight = (const float*)d_in[1];
    const float* cbias   = (const float*)d_in[2];
    const float* conv1_w = (const float*)d_in[3];
    const float* conv1_b = (const float*)d_in[4];
    const float* gn_g    = (const float*)d_in[5];
    const float* gn_b    = (const float*)d_in[6];
    const float* convh_w = (const float*)d_in[7];
    const float* convh_b = (const float*)d_in[8];
    const float* convw_w = (const float*)d_in[9];
    const float* convw_b = (const float*)d_in[10];
    float* out = (float*)d_out;

    scsa_kernel<<<512, THREADS>>>(
        x, cweight, cbias, conv1_w, conv1_b, gn_g, gn_b,
        convh_w, convh_b, convw_w, convw_b, out);
}

// round 4
// speedup vs baseline: 1.4635x; 1.4043x over previous
#include <cuda_runtime.h>

// SCSA fused v3b: persistent occ-1 CTAs + work stealing + L2-reuse-aware caching.
// (Resubmit of v3 after infra-side container failure; logic unchanged.)
// 512 work units: u<256 -> spatial unit (x1 half of block b=u),
//                 u>=256 -> channel unit (x0 half of block b=u-256).
// 152 CTAs x 1024 threads, occ 1 -> residency ~152 CTAs, per-wave reuse window
// ~152*512KB fits L2, so pass-B re-read hits L2. Stores/.last-use loads use .cs.

#define NCTAS   152
#define THREADS 1024
#define NUNITS  512

__device__ unsigned int g_counter;

__global__ void reset_counter_k() { g_counter = 0u; }

__device__ __forceinline__ float sigmoidf_(float z) {
    return 1.f / (1.f + __expf(-z));
}
__device__ __forceinline__ float sigapx_(float z) {
    float t;
    asm("tanh.approx.f32 %0, %1;" : "=f"(t) : "f"(z * 0.5f));
    return fmaf(0.5f, t, 0.5f);
}
__device__ __forceinline__ float hswishf_(float z) {
    return z * __saturatef((z + 3.f) * (1.f / 6.f));
}
__device__ __forceinline__ int shuffle_out_ch(int p) {
    return (p < 256) ? (2 * p) : (2 * (p - 256) + 1);
}

__global__ __launch_bounds__(THREADS, 1) void scsa_persistent(
    const float* __restrict__ x,
    const float* __restrict__ cweight, const float* __restrict__ cbias,
    const float* __restrict__ conv1_w, const float* __restrict__ conv1_b,
    const float* __restrict__ gn_g,    const float* __restrict__ gn_b,
    const float* __restrict__ convh_w, const float* __restrict__ convh_b,
    const float* __restrict__ convw_w, const float* __restrict__ convw_b,
    float* __restrict__ out)
{
    __shared__ float s_red[4096];   // xh(0-63)|xw(64-127) per channel; aliased as a_h|a_w
    __shared__ float s_y[4096];
    __shared__ float s_w1[1024], s_wh[1024], s_ww[1024];
    __shared__ float s_b1[32], s_bh[32], s_bw[32], s_gg[32], s_gb[32], s_xs[32];
    __shared__ unsigned s_u;
    float* s_a = s_red;

    const int tid  = threadIdx.x;
    const int wid  = tid >> 5;       // warp = channel
    const int lane = tid & 31;
    const int half = lane >> 4;      // row parity within a 2-row load step
    const int q    = lane & 15;      // float4 index within a row

    // stage weights once (loop-top __syncthreads publishes them)
    s_w1[tid & 1023] = conv1_w[tid & 1023];
    s_wh[tid & 1023] = convh_w[tid & 1023];
    s_ww[tid & 1023] = convw_w[tid & 1023];
    if (tid < 32) {
        s_b1[tid] = conv1_b[tid]; s_bh[tid] = convh_b[tid]; s_bw[tid] = convw_b[tid];
        s_gg[tid] = gn_g[tid];    s_gb[tid] = gn_b[tid];
    }

    const int c = wid;

    while (true) {
        __syncthreads();                 // smem quiesce + weight publish
        if (tid == 0) s_u = atomicAdd(&g_counter, 1u);
        __syncthreads();
        const unsigned u = s_u;
        if (u >= NUNITS) return;

        if (u < 256) {
            // ================= spatial unit: x1 of block b = u =================
            const int n = u >> 3, g = u & 7;
            const float4* xc4 = (const float4*)(x + ((size_t)(n * 512 + g * 64 + 32 + c)) * 4096);

            // ---- Pass A: row/col/total means. 4 loads in flight per warp. ----
            float cs0 = 0.f, cs1 = 0.f, cs2 = 0.f, cs3 = 0.f, xs = 0.f;
            #pragma unroll
            for (int tt = 0; tt < 32; tt += 4) {
                float4 v0 = xc4[(tt + 0) * 32 + lane];
                float4 v1 = xc4[(tt + 1) * 32 + lane];
                float4 v2 = xc4[(tt + 2) * 32 + lane];
                float4 v3 = xc4[(tt + 3) * 32 + lane];
                cs0 += (v0.x + v1.x) + (v2.x + v3.x);
                cs1 += (v0.y + v1.y) + (v2.y + v3.y);
                cs2 += (v0.z + v1.z) + (v2.z + v3.z);
                cs3 += (v0.w + v1.w) + (v2.w + v3.w);
                float r0 = (v0.x + v0.y) + (v0.z + v0.w);
                float r1 = (v1.x + v1.y) + (v1.z + v1.w);
                float r2 = (v2.x + v2.y) + (v2.z + v2.w);
                float r3 = (v3.x + v3.y) + (v3.z + v3.w);
                xs += (r0 + r1) + (r2 + r3);
                #pragma unroll
                for (int o = 8; o; o >>= 1) {      // 4 independent half-warp chains
                    r0 += __shfl_xor_sync(0xffffffffu, r0, o);
                    r1 += __shfl_xor_sync(0xffffffffu, r1, o);
                    r2 += __shfl_xor_sync(0xffffffffu, r2, o);
                    r3 += __shfl_xor_sync(0xffffffffu, r3, o);
                }
                if (q == 0) {
                    s_red[c * 128 + 2 * (tt + 0) + half] = r0 * (1.f / 64.f);
                    s_red[c * 128 + 2 * (tt + 1) + half] = r1 * (1.f / 64.f);
                    s_red[c * 128 + 2 * (tt + 2) + half] = r2 * (1.f / 64.f);
                    s_red[c * 128 + 2 * (tt + 3) + half] = r3 * (1.f / 64.f);
                }
            }
            cs0 += __shfl_xor_sync(0xffffffffu, cs0, 16);
            cs1 += __shfl_xor_sync(0xffffffffu, cs1, 16);
            cs2 += __shfl_xor_sync(0xffffffffu, cs2, 16);
            cs3 += __shfl_xor_sync(0xffffffffu, cs3, 16);
            #pragma unroll
            for (int o = 16; o; o >>= 1) xs += __shfl_xor_sync(0xffffffffu, xs, o);
            if (half == 0) {
                ((float4*)(s_red + c * 128 + 64))[q] = make_float4(
                    cs0 * (1.f / 64.f), cs1 * (1.f / 64.f),
                    cs2 * (1.f / 64.f), cs3 * (1.f / 64.f));
            }
            if (lane == 0) s_xs[c] = xs * (1.f / 4096.f);
            __syncthreads();

            // ---- conv1 ----
            #pragma unroll
            for (int k = 0; k < 4; k++) {
                const int idx = k * 1024 + tid;
                const int o = idx >> 7, p = idx & 127;
                float acc = s_b1[o];
                #pragma unroll
                for (int i = 0; i < 32; i++) acc = fmaf(s_w1[o * 32 + i], s_red[i * 128 + p], acc);
                s_y[idx] = acc;
            }
            __syncthreads();

            // ---- GroupNorm(128) + h-swish, warp per channel ----
            {
                float* yr = s_y + c * 128;
                float v0 = yr[lane], v1 = yr[lane + 32], v2 = yr[lane + 64], v3 = yr[lane + 96];
                float s1 = (v0 + v1) + (v2 + v3);
                float s2 = fmaf(v0, v0, fmaf(v1, v1, fmaf(v2, v2, v3 * v3)));
                #pragma unroll
                for (int o = 16; o; o >>= 1) {
                    s1 += __shfl_xor_sync(0xffffffffu, s1, o);
                    s2 += __shfl_xor_sync(0xffffffffu, s2, o);
                }
                const float mu  = s1 * (1.f / 128.f);
                const float var = s2 * (1.f / 128.f) - mu * mu;
                const float gm  = s_gg[c] * rsqrtf(var + 1e-5f);
                const float gc  = fmaf(-mu, gm, s_gb[c]);
                yr[lane]      = hswishf_(fmaf(v0, gm, gc));
                yr[lane + 32] = hswishf_(fmaf(v1, gm, gc));
                yr[lane + 64] = hswishf_(fmaf(v2, gm, gc));
                yr[lane + 96] = hswishf_(fmaf(v3, gm, gc));
            }
            __syncthreads();

            // ---- conv_h / conv_w -> s_a ----
            #pragma unroll
            for (int k = 0; k < 4; k++) {
                const int idx = k * 1024 + tid;
                const int o = idx >> 7, p = idx & 127;
                const float* w = (p < 64) ? (s_wh + o * 32) : (s_ww + o * 32);
                float acc = (p < 64) ? s_bh[o] : s_bw[o];
                #pragma unroll
                for (int i = 0; i < 32; i++) acc = fmaf(w[i], s_y[i * 128 + p], acc);
                s_a[idx] = acc;
            }
            __syncthreads();

            // ---- Pass B: gate + channel-shuffled store (L2-hit re-read) ----
            const float xsv = s_xs[c];
            float4 aw = ((const float4*)(s_a + c * 128 + 64))[q];
            const float g0 = aw.x * xsv, g1 = aw.y * xsv, g2 = aw.z * xsv, g3 = aw.w * xsv;
            float4* od = (float4*)(out + ((size_t)(n * 512 + shuffle_out_ch(g * 64 + 32 + c))) * 4096);
            #pragma unroll
            for (int tt = 0; tt < 32; tt += 4) {
                float4 v0 = __ldcs(&xc4[(tt + 0) * 32 + lane]);
                float4 v1 = __ldcs(&xc4[(tt + 1) * 32 + lane]);
                float4 v2 = __ldcs(&xc4[(tt + 2) * 32 + lane]);
                float4 v3 = __ldcs(&xc4[(tt + 3) * 32 + lane]);
                const float a0 = s_a[c * 128 + 2 * (tt + 0) + half];
                const float a1 = s_a[c * 128 + 2 * (tt + 1) + half];
                const float a2 = s_a[c * 128 + 2 * (tt + 2) + half];
                const float a3 = s_a[c * 128 + 2 * (tt + 3) + half];
                v0.x *= sigapx_(a0 * g0); v0.y *= sigapx_(a0 * g1);
                v0.z *= sigapx_(a0 * g2); v0.w *= sigapx_(a0 * g3);
                v1.x *= sigapx_(a1 * g0); v1.y *= sigapx_(a1 * g1);
                v1.z *= sigapx_(a1 * g2); v1.w *= sigapx_(a1 * g3);
                v2.x *= sigapx_(a2 * g0); v2.y *= sigapx_(a2 * g1);
                v2.z *= sigapx_(a2 * g2); v2.w *= sigapx_(a2 * g3);
                v3.x *= sigapx_(a3 * g0); v3.y *= sigapx_(a3 * g1);
                v3.z *= sigapx_(a3 * g2); v3.w *= sigapx_(a3 * g3);
                __stcs(&od[(tt + 0) * 32 + lane], v0);
                __stcs(&od[(tt + 1) * 32 + lane], v1);
                __stcs(&od[(tt + 2) * 32 + lane], v2);
                __stcs(&od[(tt + 3) * 32 + lane], v3);
            }
        } else {
            // ================= channel unit: x0 of block b = u-256 =================
            const int b = (int)u - 256;
            const int n = b >> 3, g = b & 7;
            const float4* xc4 = (const float4*)(x + ((size_t)(n * 512 + g * 64 + c)) * 4096);
            float s = 0.f;
            #pragma unroll
            for (int tt = 0; tt < 32; tt += 4) {
                float4 v0 = xc4[(tt + 0) * 32 + lane];
                float4 v1 = xc4[(tt + 1) * 32 + lane];
                float4 v2 = xc4[(tt + 2) * 32 + lane];
                float4 v3 = xc4[(tt + 3) * 32 + lane];
                s += ((v0.x + v0.y) + (v0.z + v0.w)) + ((v1.x + v1.y) + (v1.z + v1.w))
                   + ((v2.x + v2.y) + (v2.z + v2.w)) + ((v3.x + v3.y) + (v3.z + v3.w));
            }
            #pragma unroll
            for (int o = 16; o; o >>= 1) s += __shfl_xor_sync(0xffffffffu, s, o);
            const float gate = sigmoidf_(cweight[c] * (s * (1.f / 4096.f)) + cbias[c]);

            float4* od = (float4*)(out + ((size_t)(n * 512 + shuffle_out_ch(g * 64 + c))) * 4096);
            #pragma unroll
            for (int tt = 0; tt < 32; tt += 4) {
                float4 v0 = __ldcs(&xc4[(tt + 0) * 32 + lane]);
                float4 v1 = __ldcs(&xc4[(tt + 1) * 32 + lane]);
                float4 v2 = __ldcs(&xc4[(tt + 2) * 32 + lane]);
                float4 v3 = __ldcs(&xc4[(tt + 3) * 32 + lane]);
                v0.x *= gate; v0.y *= gate; v0.z *= gate; v0.w *= gate;
                v1.x *= gate; v1.y *= gate; v1.z *= gate; v1.w *= gate;
                v2.x *= gate; v2.y *= gate; v2.z *= gate; v2.w *= gate;
                v3.x *= gate; v3.y *= gate; v3.z *= gate; v3.w *= gate;
                __stcs(&od[(tt + 0) * 32 + lane], v0);
                __stcs(&od[(tt + 1) * 32 + lane], v1);
                __stcs(&od[(tt + 2) * 32 + lane], v2);
                __stcs(&od[(tt + 3) * 32 + lane], v3);
            }
        }
    }
}

extern "C" void kernel_launch(void* const* d_in, const int* in_sizes, int n_in,
                              void* d_out, int out_size) {
    const float* x       = (const float*)d_in[0];
    const float* cweight = (const float*)d_in[1];
    const float* cbias   = (const float*)d_in[2];
    const float* conv1_w = (const float*)d_in[3];
    const float* conv1_b = (const float*)d_in[4];
    const float* gn_g    = (const float*)d_in[5];
    const float* gn_b    = (const float*)d_in[6];
    const float* convh_w = (const float*)d_in[7];
    const float* convh_b = (const float*)d_in[8];
    const float* convw_w = (const float*)d_in[9];
    const float* convw_b = (const float*)d_in[10];
    float* out = (float*)d_out;

    reset_counter_k<<<1, 1>>>();
    scsa_persistent<<<NCTAS, THREADS>>>(
        x, cweight, cbias, conv1_w, conv1_b, gn_g, gn_b,
        convh_w, convh_b, convw_w, convw_b, out);
}